// round 6
// baseline (speedup 1.0000x reference)
#include <cuda_runtime.h>
#include <cuda_fp16.h>
#include <cstdint>

// y[b,o] = sum_j relu(w[o,j]*x_aug[b,j])
//        = 0.5*( x.w + |x|.|w| ) + relu(w[o,256])
// fp16 mma.sync m16n8k16; abs on packed fp16x2 regs; both terms -> same fp32 C.
// 512 threads / 16 warps (32x32 warp tile) to feed the HMMA pipe.

#define BM 128
#define BN 128
#define KDIM 256
#define WSTRIDE 257
#define NDIM 256

#define TILE_BYTES 16384          // 128 rows x 64 fp16 (128B rows)
#define B_OFF (2 * TILE_BYTES)    // after 2 A buffers
#define DYN_BYTES (6 * TILE_BYTES + 1024)

__device__ __forceinline__ uint32_t swz(uint32_t o) { return o ^ ((o >> 3) & 0x70u); }

__device__ __forceinline__ uint32_t smem_u32(const void* p) {
    uint32_t a;
    asm("{ .reg .u64 t; cvta.to.shared.u64 t, %1; cvt.u32.u64 %0, t; }" : "=r"(a) : "l"(p));
    return a;
}

#define LDSM4(r0, r1, r2, r3, addr) \
    asm volatile("ldmatrix.sync.aligned.m8n8.x4.shared.b16 {%0,%1,%2,%3}, [%4];" \
                 : "=r"(r0), "=r"(r1), "=r"(r2), "=r"(r3) : "r"(addr))
#define MMA16816(c, a, b0, b1) \
    asm volatile("mma.sync.aligned.m16n8k16.row.col.f32.f16.f16.f32 " \
                 "{%0,%1,%2,%3}, {%4,%5,%6,%7}, {%8,%9}, {%0,%1,%2,%3};" \
                 : "+f"((c)[0]), "+f"((c)[1]), "+f"((c)[2]), "+f"((c)[3]) \
                 : "r"((a)[0]), "r"((a)[1]), "r"((a)[2]), "r"((a)[3]), "r"(b0), "r"(b1))

// A chunk (128 x 64 fp32): per thread row = tid>>2, 16 consecutive floats
__device__ __forceinline__ void a_load(const float* __restrict__ x, int bm, int u,
                                       int tid, float4* xr) {
    const int row = tid >> 2;
    const int c0 = (tid & 3) * 16;
    const float* p = x + (size_t)(bm + row) * KDIM + u * 64 + c0;
#pragma unroll
    for (int g = 0; g < 4; g++)
        xr[g] = *reinterpret_cast<const float4*>(p + 4 * g);
}

__device__ __forceinline__ uint32_t pack_h2(float a, float b) {
    __half2 h = __floats2half2_rn(a, b);
    return *reinterpret_cast<uint32_t*>(&h);
}

// convert + store one A chunk into swizzled fp16 tile (2 x 16B stores)
__device__ __forceinline__ void a_store(char* sb, int buf, const float4* xr, int tid) {
    char* base = sb + buf * TILE_BYTES;
    const int row = tid >> 2;
    const int c0 = (tid & 3) * 16;
    const uint32_t ob = (uint32_t)(row * 128 + c0 * 2);
#pragma unroll
    for (int s = 0; s < 2; s++) {
        const float4 v0 = xr[2 * s], v1 = xr[2 * s + 1];
        uint4 st;
        st.x = pack_h2(v0.x, v0.y);
        st.y = pack_h2(v0.z, v0.w);
        st.z = pack_h2(v1.x, v1.y);
        st.w = pack_h2(v1.z, v1.w);
        *reinterpret_cast<uint4*>(base + swz(ob + 16 * s)) = st;
    }
}

__global__ __launch_bounds__(512, 1)
void skan_mma_kernel(const float* __restrict__ x,
                     const float* __restrict__ w,
                     float* __restrict__ out)
{
    extern __shared__ char dynraw[];
    __shared__ float bias_s[BN];

    char* sb = (char*)(((uintptr_t)dynraw + 1023) & ~(uintptr_t)1023);
    const uint32_t sb_u = smem_u32(sb);

    const int tid = threadIdx.x;
    const int lane = tid & 31;
    const int wid = tid >> 5;
    const int bm = blockIdx.y * BM;
    const int bn = blockIdx.x * BN;
    const int wm = wid & 3;     // warp row (4 x 32)
    const int wn = wid >> 2;    // warp col (4 x 32)

    if (tid < BN)
        bias_s[tid] = fmaxf(__ldg(w + (size_t)(bn + tid) * WSTRIDE + 256), 0.0f);

    // ---- B fill (once): w[bn..bn+127][0..255] -> 4 resident fp16 chunk tiles ----
#pragma unroll 2
    for (int j = 0; j < 8; j++) {
        const int row = wid + 16 * j;
        const float* wr = w + (size_t)(bn + row) * WSTRIDE;
#pragma unroll
        for (int h = 0; h < 8; h++) {
            const int col = lane + 32 * h;                    // coalesced across lanes
            const __half v = __float2half_rn(__ldg(wr + col));
            char* dst = sb + B_OFF + (col >> 6) * TILE_BYTES +
                        swz((uint32_t)(row * 128 + (col & 63) * 2));
            *reinterpret_cast<__half*>(dst) = v;
        }
    }

    // ---- A chunk 0 ----
    float4 xr[4];
    a_load(x, bm, 0, tid, xr);
    a_store(sb, 0, xr, tid);
    __syncthreads();

    float acc[2][4][4];
#pragma unroll
    for (int mt = 0; mt < 2; mt++)
#pragma unroll
        for (int nt = 0; nt < 4; nt++)
#pragma unroll
            for (int q = 0; q < 4; q++) acc[mt][nt][q] = 0.0f;

    int buf = 0;
#pragma unroll 1
    for (int u = 0; u < 4; u++) {
        if (u < 3) a_load(x, bm, u + 1, tid, xr);

        const uint32_t Abase = sb_u + buf * TILE_BYTES;
        const uint32_t Bbase = sb_u + B_OFF + u * TILE_BYTES;

#pragma unroll
        for (int kk = 0; kk < 4; kk++) {
            uint32_t A[2][4], Aa[2][4];
#pragma unroll
            for (int mt = 0; mt < 2; mt++) {
                const int row = wm * 32 + mt * 16 + (lane & 15);
                const int col = kk * 16 + (lane >> 4) * 8;
                const uint32_t addr = Abase + swz((uint32_t)(row * 128 + col * 2));
                LDSM4(A[mt][0], A[mt][1], A[mt][2], A[mt][3], addr);
            }
            // B: non-trans ldmatrix on [n][k] tile.
            // matrices: 0 = n0:8 k-lo, 1 = n8:16 k-lo, 2 = n0:8 k-hi, 3 = n8:16 k-hi
            uint32_t B2[2][4], Ba[2][4];
#pragma unroll
            for (int np = 0; np < 2; np++) {
                const int nrow = wn * 32 + np * 16 + (lane & 15);
                const int ncol = kk * 16 + (lane >> 4) * 8;
                const uint32_t addr = Bbase + swz((uint32_t)(nrow * 128 + ncol * 2));
                LDSM4(B2[np][0], B2[np][1], B2[np][2], B2[np][3], addr);
            }
#pragma unroll
            for (int mt = 0; mt < 2; mt++)
#pragma unroll
                for (int q = 0; q < 4; q++) Aa[mt][q] = A[mt][q] & 0x7FFF7FFFu;
#pragma unroll
            for (int np = 0; np < 2; np++)
#pragma unroll
                for (int q = 0; q < 4; q++) Ba[np][q] = B2[np][q] & 0x7FFF7FFFu;

#pragma unroll
            for (int mt = 0; mt < 2; mt++)
#pragma unroll
                for (int nt = 0; nt < 4; nt++) {
                    const int np = nt >> 1, o = nt & 1;   // o: n8-group within 16
                    MMA16816(acc[mt][nt], A[mt],  B2[np][o], B2[np][o + 2]);
                    MMA16816(acc[mt][nt], Aa[mt], Ba[np][o], Ba[np][o + 2]);
                }
        }

        if (u < 3) {
            a_store(sb, buf ^ 1, xr, tid);
            __syncthreads();
            buf ^= 1;
        }
    }

    // ---- epilogue: y = 0.5*acc + relu(bias) ----
#pragma unroll
    for (int mt = 0; mt < 2; mt++) {
#pragma unroll
        for (int nt = 0; nt < 4; nt++) {
            const int r0 = bm + wm * 32 + mt * 16 + (lane >> 2);
            const int cl = wn * 32 + nt * 8 + (lane & 3) * 2;
            const float b0 = bias_s[cl], b1 = bias_s[cl + 1];
            float2 v0, v1;
            v0.x = 0.5f * acc[mt][nt][0] + b0;
            v0.y = 0.5f * acc[mt][nt][1] + b1;
            v1.x = 0.5f * acc[mt][nt][2] + b0;
            v1.y = 0.5f * acc[mt][nt][3] + b1;
            *reinterpret_cast<float2*>(out + (size_t)r0 * NDIM + bn + cl) = v0;
            *reinterpret_cast<float2*>(out + (size_t)(r0 + 8) * NDIM + bn + cl) = v1;
        }
    }
}

extern "C" void kernel_launch(void* const* d_in, const int* in_sizes, int n_in,
                              void* d_out, int out_size)
{
    const float* x = (const float*)d_in[0];   // (8192, 256)
    const float* w = (const float*)d_in[1];   // (256, 257)
    float* out = (float*)d_out;               // (8192, 256)

    cudaFuncSetAttribute(skan_mma_kernel,
                         cudaFuncAttributeMaxDynamicSharedMemorySize, DYN_BYTES);

    dim3 grid(NDIM / BN, 8192 / BM);          // (2, 64) = 128 CTAs, one wave
    dim3 block(512);
    skan_mma_kernel<<<grid, block, DYN_BYTES>>>(x, w, out);
}